// round 15
// baseline (speedup 1.0000x reference)
#include <cuda_runtime.h>
#include <cuda_bf16.h>

#define Ww      512
#define HW      (512*512)
#define RROWS   21
#define CHUNKS  24
#define NPLANES 24
#define GRID    (NPLANES*CHUNKS)      // 576
#define XROWS   502                   // gx box rows
#define NOUTX   503                   // gx box cols
#define NOUTY   502                   // gy box cols
#define SPITCH  528                   // padded: hsum9 reads up to idx 521

__device__ double g_part[GRID][3];    // ratio, gx, gy per block
__device__ unsigned int g_ctr = 0;    // last-block counter (self-resetting)

// branch-free running 10-sum, register-resident window: thread t owns outputs
// [9t, 9t+9) and reads src[9t .. 9t+17] once into registers (stride 9 coprime
// to 32 -> conflict-free). Requires src zero-padded: max read 521 < SPITCH.
__device__ __forceinline__ void hsum9(const float* __restrict__ src,
                                      float* __restrict__ dst, int t) {
    int base = 9 * t;
    float r[18];
#pragma unroll
    for (int k = 0; k < 18; k++) r[k] = src[base + k];
    float s = 0.f;
#pragma unroll
    for (int k = 0; k < 10; k++) s += r[k];
#pragma unroll
    for (int u = 0; u < 9; u++) {
        dst[base + u] = s;
        if (u < 8) s += r[u + 10] - r[u];
    }
}

struct KtvSmem {
    float sV[2][4][SPITCH];   // [buf][VxN,VxI,VyN,VyI]
    float sSx[2][2][SPITCH];  // [buf][N,I]    Sx(r) lives in buf r&1
    float sSy[3][2][SPITCH];  // [slot][N,I]   Sy(r) lives in slot r%3
    float sred[3][8];
    double dred[3][8];
    unsigned s_rank;
};

// ratio accumulate for output row rr (requires Sx(rr), Sy(rr), Sy(rr+1) ready)
__device__ __forceinline__ void ratio_row(KtvSmem* sm, int c, int rr, float& accr) {
    int bx = rr & 1, s0 = rr % 3, s1 = (rr + 1) % 3;
#pragma unroll
    for (int oi = 0; oi < 2; oi++) {
        int o = c + oi * 256;
        if (o < NOUTX) {
            float SxN = sm->sSx[bx][0][o], SxI = sm->sSx[bx][1][o];
            int t2 = rr + o;
            float SyN, SyI;
            if (t2 < NOUTY) {
                SyN = sm->sSy[s0][0][t2]; SyI = sm->sSy[s0][1][t2];
            } else {
                int w = t2 - NOUTY;
                SyN = sm->sSy[s1][0][w]; SyI = sm->sSy[s1][1][w];
            }
            accr += __fdividef(SxN + SyN, SxI + SyI + 1e-4f);
        }
    }
}

// one pipelined phase for iteration r: store V(r), ONE sync, ratio(r-1) + hsum
// ha/ht: precomputed hsum task (array index, thread-within-array); ha<0 = idle.
template <bool DO_RATIO>
__device__ __forceinline__ void phase(KtvSmem* sm, int c, int r,
                                      const float2* Vx, const float2* VyN,
                                      float& accr, int ha, int ht) {
    int buf = r & 1, slot = (r + 1) % 3;
#pragma unroll
    for (int j = 0; j < 2; j++) {
        *reinterpret_cast<float2*>(&sm->sV[buf][j][2 * c])     = Vx[j];
        *reinterpret_cast<float2*>(&sm->sV[buf][2 + j][2 * c]) = VyN[j];
    }
    __syncthreads();
    if (DO_RATIO) ratio_row(sm, c, r - 1, accr);
    if (ha >= 0) {
        if (ha < 2) hsum9(sm->sV[buf][ha], sm->sSx[buf][ha], ht);
        else        hsum9(sm->sV[buf][ha], sm->sSy[slot][ha - 2], ht);
    }
}

__global__ __launch_bounds__(256, 4)
void ktv_kernel(const float* __restrict__ outl,
                const float* __restrict__ outr,
                const float* __restrict__ inpi,
                float* __restrict__ out) {
    __shared__ KtvSmem sm;

    const int plane = blockIdx.x / CHUNKS;
    const int chunk = blockIdx.x % CHUNKS;
    const int r0 = chunk * RROWS;
    const int r1 = min(r0 + RROWS, XROWS);
    const bool is_last = (r1 == XROWS);
    const float* __restrict__ base[3] = {
        outl + (size_t)plane * HW,
        outr + (size_t)plane * HW,
        inpi + (size_t)plane * HW };
    const int c = threadIdx.x;             // column pair (2c, 2c+1)
    const int x2i = (c < 255) ? (2 * c + 2) : 511;   // clamped col+2 index
    const bool cok = (c < 255);            // gy valid at col 2c+1
    // hoisted hsum task mapping: 4 arrays x 57 threads
    const int ha = (c < 228) ? (c / 57) : -1;
    const int ht = c % 57;

    // zero the hsum padding region [512, SPITCH) of all 8 sV arrays (once)
    if (c < 2 * 4 * (SPITCH - 512)) {
        int pad = SPITCH - 512;              // 16
        int arr = c / pad, off = c % pad;
        sm.sV[arr >> 2][arr & 3][512 + off] = 0.f;
    }

    float accr = 0.f, accgx = 0.f, accgy = 0.f;
    float2 Vx[2], Vy[2], p[3], l[3], pt[3];
    float  lx2[3], ptx2[3];
#pragma unroll
    for (int j = 0; j < 2; j++) { Vx[j] = make_float2(0.f, 0.f); Vy[j] = make_float2(0.f, 0.f); }

    // ---- bootstrap rows r0..r0+10 ----
#pragma unroll 1
    for (int k = 0; k <= 10; k++) {
        const int row = r0 + k;
        float2 v[3]; float x2[3];
#pragma unroll
        for (int j = 0; j < 3; j++) {
            const float* rp = base[j] + (size_t)row * Ww;
            v[j]  = reinterpret_cast<const float2*>(rp)[c];
            x2[j] = rp[x2i];
        }
        if (k > 0) {
            float2 g[3];
#pragma unroll
            for (int j = 0; j < 3; j++) {
                g[j].x = v[j].x - p[j].x; g[j].y = v[j].y - p[j].y;
            }
            Vx[0].x += fabsf(g[0].x) + fabsf(g[1].x);
            Vx[0].y += fabsf(g[0].y) + fabsf(g[1].y);
            Vx[1].x += fabsf(g[2].x);
            Vx[1].y += fabsf(g[2].y);
            int gr = row - 1;
            if ((gr >= r0 && gr < r1) || (is_last && gr >= XROWS))
                accgx += fabsf(g[0].x + g[1].x - g[2].x)
                       + fabsf(g[0].y + g[1].y - g[2].y);
        }
        float2 y[3];
#pragma unroll
        for (int j = 0; j < 3; j++) {
            y[j].x = v[j].y - v[j].x;
            y[j].y = x2[j] - v[j].y;
        }
        if (k < 10) {
            Vy[0].x += fabsf(y[0].x) + fabsf(y[1].x);
            Vy[0].y += fabsf(y[0].y) + fabsf(y[1].y);
            Vy[1].x += fabsf(y[2].x);
            Vy[1].y += fabsf(y[2].y);
        }
        if ((row >= r0 && row < r1) || (is_last && row >= XROWS)) {
            accgy += fabsf(y[0].x + y[1].x - y[2].x);
            if (cok) accgy += fabsf(y[0].y + y[1].y - y[2].y);
        }
#pragma unroll
        for (int j = 0; j < 3; j++) p[j] = v[j];
        if (k == 0)  { for (int j = 0; j < 3; j++) { pt[j] = v[j]; ptx2[j] = x2[j]; } }
        if (k == 10) { for (int j = 0; j < 3; j++) { l[j]  = v[j]; lx2[j]  = x2[j]; } }
    }

    // ---- prologue: hsum Vy(r0) -> sSy[r0%3] ----
    {
        int pb = (r0 + 1) & 1;
#pragma unroll
        for (int j = 0; j < 2; j++)
            *reinterpret_cast<float2*>(&sm.sV[pb][2 + j][2 * c]) = Vy[j];
        __syncthreads();
        if (c < 114) hsum9(sm.sV[pb][2 + c / 57], sm.sSy[r0 % 3][c / 57], ht);
        // no sync needed here: phase(r0) syncs before anyone reads/overwrites
    }

    // ---- peeled first output row r = r0 (no ratio yet) ----
    {
        float2 VyN[2];
        float tyN_x = 0.f, tyN_y = 0.f, ylN_x = 0.f, ylN_y = 0.f;
        float tyI_x, tyI_y, ylI_x, ylI_y;
#pragma unroll
        for (int j = 0; j < 3; j++) {
            float tx = pt[j].y - pt[j].x, ty2 = ptx2[j] - pt[j].y;
            float yx = l[j].y - l[j].x,   yy2 = lx2[j]  - l[j].y;
            if (j < 2) {
                tyN_x += fabsf(tx); tyN_y += fabsf(ty2);
                ylN_x += fabsf(yx); ylN_y += fabsf(yy2);
            } else {
                tyI_x = fabsf(tx); tyI_y = fabsf(ty2);
                ylI_x = fabsf(yx); ylI_y = fabsf(yy2);
            }
        }
        VyN[0].x = Vy[0].x - tyN_x + ylN_x;
        VyN[0].y = Vy[0].y - tyN_y + ylN_y;
        VyN[1].x = Vy[1].x - tyI_x + ylI_x;
        VyN[1].y = Vy[1].y - tyI_y + ylI_y;
        phase<false>(&sm, c, r0, Vx, VyN, accr, ha, ht);
#pragma unroll
        for (int j = 0; j < 2; j++) Vy[j] = VyN[j];
    }
    // lx2 / ptx2 are dead from here on.

    // ---- steady-state loop over output x-rows (carried row pointers) ----
    const float* pLead[3];   // row r+10
    const float* pTrail[3];  // row r
#pragma unroll
    for (int j = 0; j < 3; j++) {
        pLead[j]  = base[j] + (size_t)(r0 + 11) * Ww;
        pTrail[j] = base[j] + (size_t)(r0 + 1) * Ww;
    }
#pragma unroll 2
    for (int r = r0 + 1; r < r1; r++) {
        float2 n[3], t1[3]; float nx2[3], t1x2[3];
#pragma unroll
        for (int j = 0; j < 3; j++) {
            n[j]    = reinterpret_cast<const float2*>(pLead[j])[c];
            nx2[j]  = pLead[j][x2i];
            t1[j]   = reinterpret_cast<const float2*>(pTrail[j])[c];
            t1x2[j] = pTrail[j][x2i];
        }
        // gx: lead rows (r+9,r+10), trail rows (r-1,r)
        float2 gl[3];
#pragma unroll
        for (int j = 0; j < 3; j++) {
            gl[j].x = n[j].x - l[j].x;  gl[j].y = n[j].y - l[j].y;
        }
        {
            float2 gt0, gt1, gt2;
            gt0.x = t1[0].x - pt[0].x; gt0.y = t1[0].y - pt[0].y;
            gt1.x = t1[1].x - pt[1].x; gt1.y = t1[1].y - pt[1].y;
            gt2.x = t1[2].x - pt[2].x; gt2.y = t1[2].y - pt[2].y;
            Vx[0].x += fabsf(gl[0].x) + fabsf(gl[1].x) - fabsf(gt0.x) - fabsf(gt1.x);
            Vx[0].y += fabsf(gl[0].y) + fabsf(gl[1].y) - fabsf(gt0.y) - fabsf(gt1.y);
            Vx[1].x += fabsf(gl[2].x) - fabsf(gt2.x);
            Vx[1].y += fabsf(gl[2].y) - fabsf(gt2.y);
        }
        int g = r + 9;
        if ((g < r1) || (is_last && g >= XROWS))
            accgx += fabsf(gl[0].x + gl[1].x - gl[2].x)
                   + fabsf(gl[0].y + gl[1].y - gl[2].y);
        // gy: lead row r+10, trail row r
        float2 VyN[2];
        {
            float2 yl[3], ty[3];
#pragma unroll
            for (int j = 0; j < 3; j++) {
                yl[j].x = n[j].y - n[j].x;   yl[j].y = nx2[j] - n[j].y;
                ty[j].x = t1[j].y - t1[j].x; ty[j].y = t1x2[j] - t1[j].y;
            }
            int gy = r + 10;
            if ((gy < r1) || (is_last && gy >= XROWS)) {
                accgy += fabsf(yl[0].x + yl[1].x - yl[2].x);
                if (cok) accgy += fabsf(yl[0].y + yl[1].y - yl[2].y);
            }
            VyN[0].x = Vy[0].x + fabsf(yl[0].x) + fabsf(yl[1].x)
                               - fabsf(ty[0].x) - fabsf(ty[1].x);
            VyN[0].y = Vy[0].y + fabsf(yl[0].y) + fabsf(yl[1].y)
                               - fabsf(ty[0].y) - fabsf(ty[1].y);
            VyN[1].x = Vy[1].x + fabsf(yl[2].x) - fabsf(ty[2].x);
            VyN[1].y = Vy[1].y + fabsf(yl[2].y) - fabsf(ty[2].y);
        }
#pragma unroll
        for (int j = 0; j < 3; j++) {
            l[j] = n[j]; pt[j] = t1[j];
            pLead[j] += Ww; pTrail[j] += Ww;
        }

        phase<true>(&sm, c, r, Vx, VyN, accr, ha, ht);
#pragma unroll
        for (int j = 0; j < 2; j++) Vy[j] = VyN[j];
    }

    // ---- epilogue: ratio for the last row ----
    __syncthreads();
    ratio_row(&sm, c, r1 - 1, accr);

    // ---- block reduction -> per-block slot ----
    const unsigned fm = 0xFFFFFFFFu;
#pragma unroll
    for (int off = 16; off; off >>= 1) {
        accr  += __shfl_down_sync(fm, accr,  off);
        accgx += __shfl_down_sync(fm, accgx, off);
        accgy += __shfl_down_sync(fm, accgy, off);
    }
    int wid = c >> 5, lane = c & 31;
    if (lane == 0) { sm.sred[0][wid] = accr; sm.sred[1][wid] = accgx; sm.sred[2][wid] = accgy; }
    __syncthreads();
    if (wid == 0) {
        float a = (lane < 8) ? sm.sred[0][lane] : 0.f;
        float b = (lane < 8) ? sm.sred[1][lane] : 0.f;
        float d = (lane < 8) ? sm.sred[2][lane] : 0.f;
#pragma unroll
        for (int off = 4; off; off >>= 1) {
            a += __shfl_down_sync(fm, a, off);
            b += __shfl_down_sync(fm, b, off);
            d += __shfl_down_sync(fm, d, off);
        }
        if (lane == 0) {
            g_part[blockIdx.x][0] = (double)a;
            g_part[blockIdx.x][1] = (double)b;
            g_part[blockIdx.x][2] = (double)d;
            __threadfence();
            sm.s_rank = atomicAdd(&g_ctr, 1);
        }
    }
    __syncthreads();

    // ---- last block finalizes (and resets counter for next launch) ----
    if (sm.s_rank == GRID - 1) {
        if (c == 0) g_ctr = 0;
        double a = 0.0, b = 0.0, d = 0.0;
        for (int s = c; s < GRID; s += 256) {
            a += g_part[s][0]; b += g_part[s][1]; d += g_part[s][2];
        }
#pragma unroll
        for (int off = 16; off; off >>= 1) {
            a += __shfl_down_sync(fm, a, off);
            b += __shfl_down_sync(fm, b, off);
            d += __shfl_down_sync(fm, d, off);
        }
        if (lane == 0) { sm.dred[0][wid] = a; sm.dred[1][wid] = b; sm.dred[2][wid] = d; }
        __syncthreads();
        if (wid == 0) {
            a = (lane < 8) ? sm.dred[0][lane] : 0.0;
            b = (lane < 8) ? sm.dred[1][lane] : 0.0;
            d = (lane < 8) ? sm.dred[2][lane] : 0.0;
#pragma unroll
            for (int off = 4; off; off >>= 1) {
                a += __shfl_down_sync(fm, a, off);
                b += __shfl_down_sync(fm, b, off);
                d += __shfl_down_sync(fm, d, off);
            }
            if (lane == 0) {
                double nnorm = (double)NPLANES * 502.0 * 503.0;
                double ngx   = (double)NPLANES * 511.0 * 512.0;
                double ngy   = (double)NPLANES * 512.0 * 511.0;
                out[0] = (float)(1e-4 * (a / nnorm) + b / ngx + d / ngy);
            }
        }
    }
}

extern "C" void kernel_launch(void* const* d_in, const int* in_sizes, int n_in,
                              void* d_out, int out_size) {
    const float* outl = (const float*)d_in[0];
    const float* outr = (const float*)d_in[1];
    const float* inpi = (const float*)d_in[2];
    float* out = (float*)d_out;

    ktv_kernel<<<GRID, 256>>>(outl, outr, inpi, out);
}

// round 16
// speedup vs baseline: 1.2327x; 1.2327x over previous
#include <cuda_runtime.h>
#include <cuda_bf16.h>

#define Ww      512
#define HW      (512*512)
#define RROWS   21
#define CHUNKS  24
#define NPLANES 24
#define GRID    (NPLANES*CHUNKS)      // 576
#define XROWS   502                   // gx box rows
#define NOUTX   503                   // gx box cols
#define NOUTY   502                   // gy box cols
#define SPITCH  528                   // padded: hsum9 reads up to idx 521

__device__ double g_part[GRID][3];    // ratio, gx, gy per block
__device__ unsigned int g_ctr = 0;    // last-block counter (self-resetting)

// branch-free running 10-sum, register-resident window: thread t owns outputs
// [9t, 9t+9) and reads src[9t .. 9t+17] once into registers (stride 9 coprime
// to 32 -> conflict-free). Requires src zero-padded: max read 521 < SPITCH.
__device__ __forceinline__ void hsum9(const float* __restrict__ src,
                                      float* __restrict__ dst, int t) {
    int base = 9 * t;
    float r[18];
#pragma unroll
    for (int k = 0; k < 18; k++) r[k] = src[base + k];
    float s = 0.f;
#pragma unroll
    for (int k = 0; k < 10; k++) s += r[k];
#pragma unroll
    for (int u = 0; u < 9; u++) {
        dst[base + u] = s;
        if (u < 8) s += r[u + 10] - r[u];
    }
}

struct KtvSmem {
    float sV[2][4][SPITCH];   // [buf][VxN,VxI,VyN,VyI]
    float sSx[2][2][SPITCH];  // [buf][N,I]    Sx(r) lives in buf r&1
    float sSy[3][2][SPITCH];  // [slot][N,I]   Sy(r) lives in slot r%3
    float sred[3][8];
    double dred[3][8];
    unsigned s_rank;
};

// ratio accumulate for output row rr (requires Sx(rr), Sy(rr), Sy(rr+1) ready)
// sSy slot safety (ring of 3): concurrent hsum writes slot (rr+2)%3, distinct
// from the two slots read here.
__device__ __forceinline__ void ratio_row(KtvSmem* sm, int c, int rr, float& accr) {
    int bx = rr & 1, s0 = rr % 3, s1 = (rr + 1) % 3;
#pragma unroll
    for (int oi = 0; oi < 2; oi++) {
        int o = c + oi * 256;
        if (o < NOUTX) {
            float SxN = sm->sSx[bx][0][o], SxI = sm->sSx[bx][1][o];
            int t2 = rr + o;
            float SyN, SyI;
            if (t2 < NOUTY) {
                SyN = sm->sSy[s0][0][t2]; SyI = sm->sSy[s0][1][t2];
            } else {
                int w = t2 - NOUTY;
                SyN = sm->sSy[s1][0][w]; SyI = sm->sSy[s1][1][w];
            }
            accr += __fdividef(SxN + SyN, SxI + SyI + 1e-4f);
        }
    }
}

// one pipelined phase for iteration r: store V(r), ONE sync, ratio(r-1) + hsum
// ha/ht: precomputed hsum task (array index, thread-within-array); ha<0 = idle.
template <bool DO_RATIO>
__device__ __forceinline__ void phase(KtvSmem* sm, int c, int r,
                                      const float2* Vx, const float2* VyN,
                                      float& accr, int ha, int ht) {
    int buf = r & 1, slot = (r + 1) % 3;
#pragma unroll
    for (int j = 0; j < 2; j++) {
        *reinterpret_cast<float2*>(&sm->sV[buf][j][2 * c])     = Vx[j];
        *reinterpret_cast<float2*>(&sm->sV[buf][2 + j][2 * c]) = VyN[j];
    }
    __syncthreads();
    // ratio first: its LDS reads are independent of the hsum chain
    if (DO_RATIO) ratio_row(sm, c, r - 1, accr);
    if (ha >= 0) {
        if (ha < 2) hsum9(sm->sV[buf][ha], sm->sSx[buf][ha], ht);
        else        hsum9(sm->sV[buf][ha], sm->sSy[slot][ha - 2], ht);
    }
}

__global__ __launch_bounds__(256, 4)
void ktv_kernel(const float* __restrict__ outl,
                const float* __restrict__ outr,
                const float* __restrict__ inpi,
                float* __restrict__ out) {
    __shared__ KtvSmem sm;

    const int plane = blockIdx.x / CHUNKS;
    const int chunk = blockIdx.x % CHUNKS;
    const int r0 = chunk * RROWS;
    const int r1 = min(r0 + RROWS, XROWS);
    const bool is_last = (r1 == XROWS);
    const float* __restrict__ base[3] = {
        outl + (size_t)plane * HW,
        outr + (size_t)plane * HW,
        inpi + (size_t)plane * HW };
    const int c = threadIdx.x;             // column pair (2c, 2c+1)
    const int x2i = (c < 255) ? (2 * c + 2) : 511;   // clamped col+2 index
    const bool cok = (c < 255);            // gy valid at col 2c+1
    // hoisted hsum task mapping: 4 arrays x 57 threads
    const int ha = (c < 228) ? (c / 57) : -1;
    const int ht = c % 57;

    // zero the hsum padding region [512, SPITCH) of all 8 sV arrays (once)
    if (c < 2 * 4 * (SPITCH - 512)) {
        int pad = SPITCH - 512;              // 16
        int arr = c / pad, off = c % pad;
        sm.sV[arr >> 2][arr & 3][512 + off] = 0.f;
    }

    float accr = 0.f, accgx = 0.f, accgy = 0.f;
    float2 Vx[2], Vy[2], p[3], l[3], pt[3];
    float  lx2[3], ptx2[3];
#pragma unroll
    for (int j = 0; j < 2; j++) { Vx[j] = make_float2(0.f, 0.f); Vy[j] = make_float2(0.f, 0.f); }

    // ---- bootstrap rows r0..r0+10 ----
#pragma unroll 1
    for (int k = 0; k <= 10; k++) {
        const int row = r0 + k;
        float2 v[3]; float x2[3];
#pragma unroll
        for (int j = 0; j < 3; j++) {
            const float* rp = base[j] + (size_t)row * Ww;
            v[j]  = reinterpret_cast<const float2*>(rp)[c];
            x2[j] = rp[x2i];
        }
        if (k > 0) {
            float2 g[3];
#pragma unroll
            for (int j = 0; j < 3; j++) {
                g[j].x = v[j].x - p[j].x; g[j].y = v[j].y - p[j].y;
            }
            Vx[0].x += fabsf(g[0].x) + fabsf(g[1].x);
            Vx[0].y += fabsf(g[0].y) + fabsf(g[1].y);
            Vx[1].x += fabsf(g[2].x);
            Vx[1].y += fabsf(g[2].y);
            int gr = row - 1;
            if ((gr >= r0 && gr < r1) || (is_last && gr >= XROWS))
                accgx += fabsf(g[0].x + g[1].x - g[2].x)
                       + fabsf(g[0].y + g[1].y - g[2].y);
        }
        float2 y[3];
#pragma unroll
        for (int j = 0; j < 3; j++) {
            y[j].x = v[j].y - v[j].x;
            y[j].y = x2[j] - v[j].y;
        }
        if (k < 10) {
            Vy[0].x += fabsf(y[0].x) + fabsf(y[1].x);
            Vy[0].y += fabsf(y[0].y) + fabsf(y[1].y);
            Vy[1].x += fabsf(y[2].x);
            Vy[1].y += fabsf(y[2].y);
        }
        if ((row >= r0 && row < r1) || (is_last && row >= XROWS)) {
            accgy += fabsf(y[0].x + y[1].x - y[2].x);
            if (cok) accgy += fabsf(y[0].y + y[1].y - y[2].y);
        }
#pragma unroll
        for (int j = 0; j < 3; j++) p[j] = v[j];
        if (k == 0)  { for (int j = 0; j < 3; j++) { pt[j] = v[j]; ptx2[j] = x2[j]; } }
        if (k == 10) { for (int j = 0; j < 3; j++) { l[j]  = v[j]; lx2[j]  = x2[j]; } }
    }

    // ---- prologue: hsum Vy(r0) -> sSy[r0%3] ----
    {
        int pb = (r0 + 1) & 1;
#pragma unroll
        for (int j = 0; j < 2; j++)
            *reinterpret_cast<float2*>(&sm.sV[pb][2 + j][2 * c]) = Vy[j];
        __syncthreads();
        if (c < 114) hsum9(sm.sV[pb][2 + c / 57], sm.sSy[r0 % 3][c / 57], ht);
        // no sync needed here: phase(r0) syncs before anyone reads/overwrites
    }

    // ---- peeled first output row r = r0 (no ratio yet) ----
    {
        float2 VyN[2];
        float tyN_x = 0.f, tyN_y = 0.f, ylN_x = 0.f, ylN_y = 0.f;
        float tyI_x, tyI_y, ylI_x, ylI_y;
#pragma unroll
        for (int j = 0; j < 3; j++) {
            float tx = pt[j].y - pt[j].x, ty2 = ptx2[j] - pt[j].y;
            float yx = l[j].y - l[j].x,   yy2 = lx2[j]  - l[j].y;
            if (j < 2) {
                tyN_x += fabsf(tx); tyN_y += fabsf(ty2);
                ylN_x += fabsf(yx); ylN_y += fabsf(yy2);
            } else {
                tyI_x = fabsf(tx); tyI_y = fabsf(ty2);
                ylI_x = fabsf(yx); ylI_y = fabsf(yy2);
            }
        }
        VyN[0].x = Vy[0].x - tyN_x + ylN_x;
        VyN[0].y = Vy[0].y - tyN_y + ylN_y;
        VyN[1].x = Vy[1].x - tyI_x + ylI_x;
        VyN[1].y = Vy[1].y - tyI_y + ylI_y;
        phase<false>(&sm, c, r0, Vx, VyN, accr, ha, ht);
#pragma unroll
        for (int j = 0; j < 2; j++) Vy[j] = VyN[j];
    }
    // lx2 / ptx2 are dead from here on.

    // ---- steady-state loop over output x-rows ----
#pragma unroll 1
    for (int r = r0 + 1; r < r1; r++) {
        float2 n[3], t1[3]; float nx2[3], t1x2[3];
#pragma unroll
        for (int j = 0; j < 3; j++) {
            const float* rpn = base[j] + (size_t)(r + 10) * Ww;
            const float* rpt = base[j] + (size_t)r * Ww;
            n[j]   = reinterpret_cast<const float2*>(rpn)[c];
            nx2[j] = rpn[x2i];
            t1[j]  = reinterpret_cast<const float2*>(rpt)[c];
            t1x2[j]= rpt[x2i];
        }
        // gx: lead rows (r+9,r+10), trail rows (r-1,r)
        float2 gl[3];
#pragma unroll
        for (int j = 0; j < 3; j++) {
            gl[j].x = n[j].x - l[j].x;  gl[j].y = n[j].y - l[j].y;
        }
        {
            float2 gt0, gt1, gt2;
            gt0.x = t1[0].x - pt[0].x; gt0.y = t1[0].y - pt[0].y;
            gt1.x = t1[1].x - pt[1].x; gt1.y = t1[1].y - pt[1].y;
            gt2.x = t1[2].x - pt[2].x; gt2.y = t1[2].y - pt[2].y;
            Vx[0].x += fabsf(gl[0].x) + fabsf(gl[1].x) - fabsf(gt0.x) - fabsf(gt1.x);
            Vx[0].y += fabsf(gl[0].y) + fabsf(gl[1].y) - fabsf(gt0.y) - fabsf(gt1.y);
            Vx[1].x += fabsf(gl[2].x) - fabsf(gt2.x);
            Vx[1].y += fabsf(gl[2].y) - fabsf(gt2.y);
        }
        int g = r + 9;
        if ((g < r1) || (is_last && g >= XROWS))
            accgx += fabsf(gl[0].x + gl[1].x - gl[2].x)
                   + fabsf(gl[0].y + gl[1].y - gl[2].y);
        // gy: lead row r+10, trail row r
        float2 VyN[2];
        {
            float2 yl[3], ty[3];
#pragma unroll
            for (int j = 0; j < 3; j++) {
                yl[j].x = n[j].y - n[j].x;   yl[j].y = nx2[j] - n[j].y;
                ty[j].x = t1[j].y - t1[j].x; ty[j].y = t1x2[j] - t1[j].y;
            }
            int gy = r + 10;
            if ((gy < r1) || (is_last && gy >= XROWS)) {
                accgy += fabsf(yl[0].x + yl[1].x - yl[2].x);
                if (cok) accgy += fabsf(yl[0].y + yl[1].y - yl[2].y);
            }
            VyN[0].x = Vy[0].x + fabsf(yl[0].x) + fabsf(yl[1].x)
                               - fabsf(ty[0].x) - fabsf(ty[1].x);
            VyN[0].y = Vy[0].y + fabsf(yl[0].y) + fabsf(yl[1].y)
                               - fabsf(ty[0].y) - fabsf(ty[1].y);
            VyN[1].x = Vy[1].x + fabsf(yl[2].x) - fabsf(ty[2].x);
            VyN[1].y = Vy[1].y + fabsf(yl[2].y) - fabsf(ty[2].y);
        }
#pragma unroll
        for (int j = 0; j < 3; j++) { l[j] = n[j]; pt[j] = t1[j]; }

        phase<true>(&sm, c, r, Vx, VyN, accr, ha, ht);
#pragma unroll
        for (int j = 0; j < 2; j++) Vy[j] = VyN[j];
    }

    // ---- epilogue: ratio for the last row ----
    __syncthreads();
    ratio_row(&sm, c, r1 - 1, accr);

    // ---- block reduction -> per-block slot ----
    const unsigned fm = 0xFFFFFFFFu;
#pragma unroll
    for (int off = 16; off; off >>= 1) {
        accr  += __shfl_down_sync(fm, accr,  off);
        accgx += __shfl_down_sync(fm, accgx, off);
        accgy += __shfl_down_sync(fm, accgy, off);
    }
    int wid = c >> 5, lane = c & 31;
    if (lane == 0) { sm.sred[0][wid] = accr; sm.sred[1][wid] = accgx; sm.sred[2][wid] = accgy; }
    __syncthreads();
    if (wid == 0) {
        float a = (lane < 8) ? sm.sred[0][lane] : 0.f;
        float b = (lane < 8) ? sm.sred[1][lane] : 0.f;
        float d = (lane < 8) ? sm.sred[2][lane] : 0.f;
#pragma unroll
        for (int off = 4; off; off >>= 1) {
            a += __shfl_down_sync(fm, a, off);
            b += __shfl_down_sync(fm, b, off);
            d += __shfl_down_sync(fm, d, off);
        }
        if (lane == 0) {
            g_part[blockIdx.x][0] = (double)a;
            g_part[blockIdx.x][1] = (double)b;
            g_part[blockIdx.x][2] = (double)d;
            __threadfence();
            sm.s_rank = atomicAdd(&g_ctr, 1);
        }
    }
    __syncthreads();

    // ---- last block finalizes (and resets counter for next launch) ----
    if (sm.s_rank == GRID - 1) {
        if (c == 0) g_ctr = 0;
        double a = 0.0, b = 0.0, d = 0.0;
        for (int s = c; s < GRID; s += 256) {
            a += g_part[s][0]; b += g_part[s][1]; d += g_part[s][2];
        }
#pragma unroll
        for (int off = 16; off; off >>= 1) {
            a += __shfl_down_sync(fm, a, off);
            b += __shfl_down_sync(fm, b, off);
            d += __shfl_down_sync(fm, d, off);
        }
        if (lane == 0) { sm.dred[0][wid] = a; sm.dred[1][wid] = b; sm.dred[2][wid] = d; }
        __syncthreads();
        if (wid == 0) {
            a = (lane < 8) ? sm.dred[0][lane] : 0.0;
            b = (lane < 8) ? sm.dred[1][lane] : 0.0;
            d = (lane < 8) ? sm.dred[2][lane] : 0.0;
#pragma unroll
            for (int off = 4; off; off >>= 1) {
                a += __shfl_down_sync(fm, a, off);
                b += __shfl_down_sync(fm, b, off);
                d += __shfl_down_sync(fm, d, off);
            }
            if (lane == 0) {
                double nnorm = (double)NPLANES * 502.0 * 503.0;
                double ngx   = (double)NPLANES * 511.0 * 512.0;
                double ngy   = (double)NPLANES * 512.0 * 511.0;
                out[0] = (float)(1e-4 * (a / nnorm) + b / ngx + d / ngy);
            }
        }
    }
}

extern "C" void kernel_launch(void* const* d_in, const int* in_sizes, int n_in,
                              void* d_out, int out_size) {
    const float* outl = (const float*)d_in[0];
    const float* outr = (const float*)d_in[1];
    const float* inpi = (const float*)d_in[2];
    float* out = (float*)d_out;

    ktv_kernel<<<GRID, 256>>>(outl, outr, inpi, out);
}